// round 13
// baseline (speedup 1.0000x reference)
#include <cuda_runtime.h>
#include <cuda_bf16.h>
#include <cstdint>

#define N_NODES 50000
#define N_EDGES 320000
#define GSCAN   ((N_NODES + 1023) / 1024)

typedef __nv_bfloat16 bf16;

// ---------------- static scratch (no allocations allowed) ----------------
__device__ bf16  g_Ahi[(size_t)N_NODES * 1024];   // activation buffer A (hi)
__device__ bf16  g_Alo[(size_t)N_NODES * 1024];   // activation buffer A (lo)
__device__ bf16  g_Bhi[(size_t)N_NODES * 2048];   // activation buffer B (hi)
__device__ bf16  g_Blo[(size_t)N_NODES * 2048];   // activation buffer B (lo)
__device__ float g_tmp[(size_t)N_NODES * 1024];   // GEMM fp32 out (pre-agg), max d=1024
__device__ bf16  g_Whi[4 * 1024 * 1024];          // transposed weights hi
__device__ bf16  g_Wlo[4 * 1024 * 1024];          // transposed weights lo

__device__ int   g_deg[N_NODES];
__device__ float g_dinv[N_NODES];
__device__ int   g_rowptr[N_NODES + 1];
__device__ int   g_fill[N_NODES];
__device__ int   g_csr[N_EDGES];
__device__ int   g_bsum[64];
__device__ int   g_is64;

// ---------------- index dtype handling ----------------
__global__ void detect_idx_kernel(const void* e) {
    const int* w = (const int*)e;
    int all0 = 1;
    for (int i = 1; i < 64; i += 2)
        if (w[i] != 0) all0 = 0;
    g_is64 = all0;
}

__device__ __forceinline__ int get_idx(const void* e, long long i) {
    if (g_is64) return (int)((const long long*)e)[i];
    return ((const int*)e)[i];
}

// ---------------- graph preprocessing ----------------
__global__ void zero_deg_kernel() {
    int i = blockIdx.x * blockDim.x + threadIdx.x;
    if (i < N_NODES) g_deg[i] = 0;
}

__global__ void count_deg_kernel(const void* e) {
    int i = blockIdx.x * blockDim.x + threadIdx.x;
    if (i >= N_EDGES) return;
    int dst = get_idx(e, (long long)N_EDGES + i);
    atomicAdd(&g_deg[dst], 1);
}

__global__ void block_sum_kernel() {
    int i = blockIdx.x * 1024 + threadIdx.x;
    int v = (i < N_NODES) ? g_deg[i] : 0;
    int lane = threadIdx.x & 31, warp = threadIdx.x >> 5;
#pragma unroll
    for (int off = 16; off > 0; off >>= 1) v += __shfl_down_sync(0xffffffffu, v, off);
    __shared__ int ws[32];
    if (lane == 0) ws[warp] = v;
    __syncthreads();
    if (warp == 0) {
        int s = ws[lane];
#pragma unroll
        for (int off = 16; off > 0; off >>= 1) s += __shfl_down_sync(0xffffffffu, s, off);
        if (lane == 0) g_bsum[blockIdx.x] = s;
    }
}

__global__ void scan_partials_kernel() {
    int acc = 0;
    for (int i = 0; i < GSCAN; i++) { int t = g_bsum[i]; g_bsum[i] = acc; acc += t; }
    g_rowptr[N_NODES] = acc;
}

__global__ void scatter_scan_kernel() {
    int i = blockIdx.x * 1024 + threadIdx.x;
    int v = (i < N_NODES) ? g_deg[i] : 0;
    int lane = threadIdx.x & 31, warp = threadIdx.x >> 5;
    int incl = v;
#pragma unroll
    for (int off = 1; off < 32; off <<= 1) {
        int t = __shfl_up_sync(0xffffffffu, incl, off);
        if (lane >= off) incl += t;
    }
    __shared__ int ws[32];
    if (lane == 31) ws[warp] = incl;
    __syncthreads();
    if (warp == 0) {
        int s = ws[lane];
#pragma unroll
        for (int off = 1; off < 32; off <<= 1) {
            int t = __shfl_up_sync(0xffffffffu, s, off);
            if (lane >= off) s += t;
        }
        ws[lane] = s;
    }
    __syncthreads();
    int wbase = (warp == 0) ? 0 : ws[warp - 1];
    int excl = g_bsum[blockIdx.x] + wbase + incl - v;
    if (i < N_NODES) {
        g_rowptr[i] = excl;
        g_fill[i]   = excl;
        g_dinv[i]   = rsqrtf((float)v + 1.0f);
    }
}

__global__ void fill_csr_kernel(const void* e) {
    int i = blockIdx.x * blockDim.x + threadIdx.x;
    if (i >= N_EDGES) return;
    int src = get_idx(e, i);
    int dst = get_idx(e, (long long)N_EDGES + i);
    int pos = atomicAdd(&g_fill[dst], 1);
    g_csr[pos] = src;
}

// ---------------- weight conversion: W [K,N] -> Wt [N,K] hi/lo ----------------
__global__ void convert_w_kernel(const float* __restrict__ W, long long off, int K, int N) {
    int idx = blockIdx.x * blockDim.x + threadIdx.x;
    if (idx >= K * N) return;
    int k = idx / N, n = idx % N;
    float v = W[idx];
    bf16 h = __float2bfloat16(v);
    g_Whi[off + (size_t)n * K + k] = h;
    g_Wlo[off + (size_t)n * K + k] = __float2bfloat16(v - __bfloat162float(h));
}

// ---------------- bf16-split tensor-core GEMM (mma.sync) ----------------
// C[M,N] = A[M,K] @ Wt[N,K]^T using acc += ahi*bhi + ahi*blo + alo*bhi
// 256x128x32 tiles, 512 threads (16 warps 4x4, warp tile 64x32), cp.async
// 2-stage, xor-swizzled smem + ldmatrix.x4, mma.sync.m16n8k16 bf16.
// Tall BM=256 halves weight-panel L2 re-reads vs BM=128.
// mode 0: store fp32 C.  mode 1: fused bias+relu+bf16 hi/lo split into Ohi/Olo.
__device__ __forceinline__ void ldm4(uint32_t* r, uint32_t addr) {
    asm volatile("ldmatrix.sync.aligned.m8n8.x4.shared.b16 {%0,%1,%2,%3}, [%4];"
                 : "=r"(r[0]), "=r"(r[1]), "=r"(r[2]), "=r"(r[3]) : "r"(addr));
}

__device__ __forceinline__ void mma16816(float* c, const uint32_t* a, const uint32_t* b) {
    asm volatile(
        "mma.sync.aligned.m16n8k16.row.col.f32.bf16.bf16.f32 "
        "{%0,%1,%2,%3},{%4,%5,%6,%7},{%8,%9},{%0,%1,%2,%3};"
        : "+f"(c[0]), "+f"(c[1]), "+f"(c[2]), "+f"(c[3])
        : "r"(a[0]), "r"(a[1]), "r"(a[2]), "r"(a[3]), "r"(b[0]), "r"(b[1]));
}

__device__ __forceinline__ void cp16(uint32_t dst, const void* src, bool pred) {
    int sz = pred ? 16 : 0;
    asm volatile("cp.async.cg.shared.global [%0], [%1], 16, %2;\n"
                 :: "r"(dst), "l"(src), "r"(sz));
}

// stage layout (48KB): Ahi[0,16K) Alo[16K,32K) Bhi[32K,40K) Blo[40K,48K)
#define STG 49152

__device__ __forceinline__ void load_stage(
    uint32_t sbase, int stage,
    const bf16* __restrict__ Ahi, const bf16* __restrict__ Alo,
    const bf16* __restrict__ Bhi, const bf16* __restrict__ Blo,
    int bm, int bn, int k0, int M, int K, int tid)
{
    uint32_t st = sbase + stage * STG;
    // A: 256 rows x 4 chunks, hi+lo  (1024 positions / 512 threads = 2 iters)
#pragma unroll
    for (int h = 0; h < 2; h++) {
        int i = tid + h * 512;
        int row = i >> 2, chunk = i & 3;
        uint32_t doff = (uint32_t)(row * 32 + (chunk ^ ((row >> 1) & 3)) * 8) * 2;
        long arow = bm + row;
        bool av = arow < M;
        long arowc = av ? arow : 0;
        cp16(st + doff, Ahi + (size_t)arowc * K + k0 + chunk * 8, av);
        cp16(st + 16384 + doff, Alo + (size_t)arowc * K + k0 + chunk * 8, av);
    }
    // B: 128 rows x 4 chunks, hi+lo (512 positions, 1 iter)
    {
        int row = tid >> 2, chunk = tid & 3;
        uint32_t doff = (uint32_t)(row * 32 + (chunk ^ ((row >> 1) & 3)) * 8) * 2;
        cp16(st + 32768 + doff, Bhi + (size_t)(bn + row) * K + k0 + chunk * 8, true);
        cp16(st + 40960 + doff, Blo + (size_t)(bn + row) * K + k0 + chunk * 8, true);
    }
    asm volatile("cp.async.commit_group;\n");
}

__global__ void __launch_bounds__(512)
bgemm_kernel(const bf16* __restrict__ Ahi, const bf16* __restrict__ Alo,
             const bf16* __restrict__ Bhi, const bf16* __restrict__ Blo,
             float* __restrict__ C, const float* __restrict__ bias,
             bf16* __restrict__ Ohi, bf16* __restrict__ Olo,
             int M, int N, int K, int mode)
{
    extern __shared__ __align__(16) char smem[];
    uint32_t sbase = (uint32_t)__cvta_generic_to_shared(smem);

    int tid  = threadIdx.x;
    int lane = tid & 31, wid = tid >> 5;
    int wm = (wid >> 2) * 64;     // 4 warp rows x 64
    int wn = (wid & 3) * 32;      // 4 warp cols x 32
    int bm = blockIdx.y * 256;
    int bn = blockIdx.x * 128;

    float acc[4][4][4];
#pragma unroll
    for (int i = 0; i < 4; i++)
#pragma unroll
        for (int j = 0; j < 4; j++)
#pragma unroll
            for (int r = 0; r < 4; r++) acc[i][j][r] = 0.f;

    int nk = K >> 5;
    load_stage(sbase, 0, Ahi, Alo, Bhi, Blo, bm, bn, 0, M, K, tid);

    int lr = lane & 15, lc = lane >> 4;

    for (int kt = 0; kt < nk; kt++) {
        if (kt + 1 < nk) {
            load_stage(sbase, (kt + 1) & 1, Ahi, Alo, Bhi, Blo, bm, bn, (kt + 1) * 32, M, K, tid);
            asm volatile("cp.async.wait_group 1;\n");
        } else {
            asm volatile("cp.async.wait_group 0;\n");
        }
        __syncthreads();

        uint32_t st = sbase + (kt & 1) * STG;
#pragma unroll
        for (int kk = 0; kk < 32; kk += 16) {
            int k = kk + lc * 8;
            // B fragments first (16 regs live)
            uint32_t bh[4][2], bl[4][2];
#pragma unroll
            for (int p = 0; p < 2; p++) {
                int row = wn + p * 16 + lr;
                uint32_t off = (uint32_t)(row * 32 + (((k >> 3) ^ ((row >> 1) & 3)) << 3)) * 2;
                uint32_t rh[4], rl[4];
                ldm4(rh, st + 32768 + off);
                ldm4(rl, st + 40960 + off);
                bh[p * 2][0] = rh[0]; bh[p * 2][1] = rh[2];
                bh[p * 2 + 1][0] = rh[1]; bh[p * 2 + 1][1] = rh[3];
                bl[p * 2][0] = rl[0]; bl[p * 2][1] = rl[2];
                bl[p * 2 + 1][0] = rl[1]; bl[p * 2 + 1][1] = rl[3];
            }
            // per-fm: load A frags (8 regs) and issue its 12 MMAs
#pragma unroll
            for (int fm = 0; fm < 4; fm++) {
                int row = wm + fm * 16 + lr;
                uint32_t off = (uint32_t)(row * 32 + (((k >> 3) ^ ((row >> 1) & 3)) << 3)) * 2;
                uint32_t ah[4], al[4];
                ldm4(ah, st + off);
                ldm4(al, st + 16384 + off);
#pragma unroll
                for (int fn = 0; fn < 4; fn++) {
                    mma16816(acc[fm][fn], ah, bh[fn]);
                    mma16816(acc[fm][fn], ah, bl[fn]);
                    mma16816(acc[fm][fn], al, bh[fn]);
                }
            }
        }
        __syncthreads();
    }

    int g = lane >> 2, tg = lane & 3;
    if (mode == 0) {
#pragma unroll
        for (int fm = 0; fm < 4; fm++) {
#pragma unroll
            for (int fn = 0; fn < 4; fn++) {
                int row = bm + wm + fm * 16 + g;
                int col = bn + wn + fn * 8 + tg * 2;
                if (row < M)
                    *(float2*)&C[(size_t)row * N + col] = make_float2(acc[fm][fn][0], acc[fm][fn][1]);
                if (row + 8 < M)
                    *(float2*)&C[(size_t)(row + 8) * N + col] = make_float2(acc[fm][fn][2], acc[fm][fn][3]);
            }
        }
    } else {
#pragma unroll
        for (int fm = 0; fm < 4; fm++) {
#pragma unroll
            for (int fn = 0; fn < 4; fn++) {
                int col = bn + wn + fn * 8 + tg * 2;
                float2 bv = *(const float2*)&bias[col];
#pragma unroll
                for (int h = 0; h < 2; h++) {
                    int row = bm + wm + fm * 16 + g + h * 8;
                    if (row >= M) continue;
                    float v0 = fmaxf(acc[fm][fn][h * 2]     + bv.x, 0.f);
                    float v1 = fmaxf(acc[fm][fn][h * 2 + 1] + bv.y, 0.f);
                    bf16 h0 = __float2bfloat16(v0);
                    bf16 h1 = __float2bfloat16(v1);
                    __nv_bfloat162 hh; hh.x = h0; hh.y = h1;
                    *(__nv_bfloat162*)&Ohi[(size_t)row * N + col] = hh;
                    __nv_bfloat162 ll;
                    ll.x = __float2bfloat16(v0 - __bfloat162float(h0));
                    ll.y = __float2bfloat16(v1 - __bfloat162float(h1));
                    *(__nv_bfloat162*)&Olo[(size_t)row * N + col] = ll;
                }
            }
        }
    }
}

// ---------------- aggregation of raw input x (d=512, fp32) -> bf16 hi/lo ----------------
__global__ void __launch_bounds__(128)
aggx_kernel(const float* __restrict__ x, bf16* __restrict__ ohi, bf16* __restrict__ olo)
{
    const int d = 512;
    int node = blockIdx.x;
    int tid  = threadIdx.x;
    float di = g_dinv[node];
    int beg = g_rowptr[node];
    int end = g_rowptr[node + 1];

    float selfn = di * di;
    float4 v = ((const float4*)(x + (size_t)node * d))[tid];
    float4 acc = make_float4(v.x * selfn, v.y * selfn, v.z * selfn, v.w * selfn);

    for (int e = beg; e < end; e++) {
        int src = g_csr[e];
        float nrm = di * g_dinv[src];
        float4 w = ((const float4*)(x + (size_t)src * d))[tid];
        acc.x += w.x * nrm; acc.y += w.y * nrm;
        acc.z += w.z * nrm; acc.w += w.w * nrm;
    }

    bf16 h0 = __float2bfloat16(acc.x), h1 = __float2bfloat16(acc.y);
    bf16 h2 = __float2bfloat16(acc.z), h3 = __float2bfloat16(acc.w);
    __nv_bfloat162 hh01; hh01.x = h0; hh01.y = h1;
    __nv_bfloat162 hh23; hh23.x = h2; hh23.y = h3;
    ((__nv_bfloat162*)(ohi + (size_t)node * d))[2 * tid]     = hh01;
    ((__nv_bfloat162*)(ohi + (size_t)node * d))[2 * tid + 1] = hh23;
    __nv_bfloat162 ll01, ll23;
    ll01.x = __float2bfloat16(acc.x - __bfloat162float(h0));
    ll01.y = __float2bfloat16(acc.y - __bfloat162float(h1));
    ll23.x = __float2bfloat16(acc.z - __bfloat162float(h2));
    ll23.y = __float2bfloat16(acc.w - __bfloat162float(h3));
    ((__nv_bfloat162*)(olo + (size_t)node * d))[2 * tid]     = ll01;
    ((__nv_bfloat162*)(olo + (size_t)node * d))[2 * tid + 1] = ll23;
}

// ---------------- CSR aggregation, wide (d = 512 or 1024), block per node --------
__global__ void __launch_bounds__(128)
agg_wide_kernel(const float* __restrict__ tmp, const float* __restrict__ bias,
                bf16* __restrict__ ohi, bf16* __restrict__ olo, int d)
{
    int node = blockIdx.x;
    int tid  = threadIdx.x;
    float di = g_dinv[node];
    int beg = g_rowptr[node];
    int end = g_rowptr[node + 1];
    int nc4 = d >> 2;

    float4 acc[2];
    float selfn = di * di;
    const float4* selfrow = (const float4*)(tmp + (size_t)node * d);
#pragma unroll
    for (int j = 0; j < 2; j++) {
        int c = tid + j * 128;
        if (c < nc4) {
            float4 v = selfrow[c];
            acc[j] = make_float4(v.x * selfn, v.y * selfn, v.z * selfn, v.w * selfn);
        } else acc[j] = make_float4(0.f, 0.f, 0.f, 0.f);
    }

    for (int e = beg; e < end; e++) {
        int src = g_csr[e];
        float nrm = di * g_dinv[src];
        const float4* row = (const float4*)(tmp + (size_t)src * d);
#pragma unroll
        for (int j = 0; j < 2; j++) {
            int c = tid + j * 128;
            if (c < nc4) {
                float4 v = row[c];
                acc[j].x += v.x * nrm; acc[j].y += v.y * nrm;
                acc[j].z += v.z * nrm; acc[j].w += v.w * nrm;
            }
        }
    }

    const float4* b4 = (const float4*)bias;
#pragma unroll
    for (int j = 0; j < 2; j++) {
        int c = tid + j * 128;
        if (c >= nc4) continue;
        float4 bv = b4[c];
        float4 r = make_float4(fmaxf(acc[j].x + bv.x, 0.f), fmaxf(acc[j].y + bv.y, 0.f),
                               fmaxf(acc[j].z + bv.z, 0.f), fmaxf(acc[j].w + bv.w, 0.f));
        bf16 h0 = __float2bfloat16(r.x), h1 = __float2bfloat16(r.y);
        bf16 h2 = __float2bfloat16(r.z), h3 = __float2bfloat16(r.w);
        __nv_bfloat162 hh01; hh01.x = h0; hh01.y = h1;
        __nv_bfloat162 hh23; hh23.x = h2; hh23.y = h3;
        ((__nv_bfloat162*)(ohi + (size_t)node * d))[2 * c]     = hh01;
        ((__nv_bfloat162*)(ohi + (size_t)node * d))[2 * c + 1] = hh23;
        __nv_bfloat162 ll01, ll23;
        ll01.x = __float2bfloat16(r.x - __bfloat162float(h0));
        ll01.y = __float2bfloat16(r.y - __bfloat162float(h1));
        ll23.x = __float2bfloat16(r.z - __bfloat162float(h2));
        ll23.y = __float2bfloat16(r.w - __bfloat162float(h3));
        ((__nv_bfloat162*)(olo + (size_t)node * d))[2 * c]     = ll01;
        ((__nv_bfloat162*)(olo + (size_t)node * d))[2 * c + 1] = ll23;
    }
}

// ---------------- CSR aggregation, narrow (d = 128 or 256), warp per node --------
__global__ void __launch_bounds__(128)
agg_narrow_kernel(const float* __restrict__ tmp, const float* __restrict__ bias,
                  float* __restrict__ outf, bf16* __restrict__ ohi,
                  bf16* __restrict__ olo, int d, int last)
{
    int node = blockIdx.x * 4 + (threadIdx.x >> 5);
    if (node >= N_NODES) return;
    int lane = threadIdx.x & 31;
    int nc4 = d >> 2;   // 32 or 64
    float di = g_dinv[node];
    int beg = g_rowptr[node];
    int end = g_rowptr[node + 1];

    float4 acc[2];
    float selfn = di * di;
    const float4* selfrow = (const float4*)(tmp + (size_t)node * d);
#pragma unroll
    for (int j = 0; j < 2; j++) {
        int c = lane + j * 32;
        if (c < nc4) {
            float4 v = selfrow[c];
            acc[j] = make_float4(v.x * selfn, v.y * selfn, v.z * selfn, v.w * selfn);
        } else acc[j] = make_float4(0.f, 0.f, 0.f, 0.f);
    }

    for (int e = beg; e < end; e++) {
        int src = g_csr[e];
        float nrm = di * g_dinv[src];
        const float4* row = (const float4*)(tmp + (size_t)src * d);
#pragma unroll
        for (int j = 0; j < 2; j++) {
            int c = lane + j * 32;
            if (c < nc4) {
                float4 v = row[c];
                acc[j].x += v.x * nrm; acc[j].y += v.y * nrm;
                acc[j].z += v.z * nrm; acc[j].w += v.w * nrm;
            }
        }
    }

    const float4* b4 = (const float4*)bias;
#pragma unroll
    for (int j = 0; j < 2; j++) {
        int c = lane + j * 32;
        if (c >= nc4) continue;
        float4 bv = b4[c];
        float4 r = make_float4(acc[j].x + bv.x, acc[j].y + bv.y,
                               acc[j].z + bv.z, acc[j].w + bv.w);
        if (last) {
            ((float4*)(outf + (size_t)node * d))[c] = r;
        } else {
            r.x = fmaxf(r.x, 0.f); r.y = fmaxf(r.y, 0.f);
            r.z = fmaxf(r.z, 0.f); r.w = fmaxf(r.w, 0.f);
            bf16 h0 = __float2bfloat16(r.x), h1 = __float2bfloat16(r.y);
            bf16 h2 = __float2bfloat16(r.z), h3 = __float2bfloat16(r.w);
            __nv_bfloat162 hh01; hh01.x = h0; hh01.y = h1;
            __nv_bfloat162 hh23; hh23.x = h2; hh23.y = h3;
            ((__nv_bfloat162*)(ohi + (size_t)node * d))[2 * c]     = hh01;
            ((__nv_bfloat162*)(ohi + (size_t)node * d))[2 * c + 1] = hh23;
            __nv_bfloat162 ll01, ll23;
            ll01.x = __float2bfloat16(r.x - __bfloat162float(h0));
            ll01.y = __float2bfloat16(r.y - __bfloat162float(h1));
            ll23.x = __float2bfloat16(r.z - __bfloat162float(h2));
            ll23.y = __float2bfloat16(r.w - __bfloat162float(h3));
            ((__nv_bfloat162*)(olo + (size_t)node * d))[2 * c]     = ll01;
            ((__nv_bfloat162*)(olo + (size_t)node * d))[2 * c + 1] = ll23;
        }
    }
}

// ---------------- launch ----------------
extern "C" void kernel_launch(void* const* d_in, const int* in_sizes, int n_in,
                              void* d_out, int out_size) {
    const float* x = (const float*)d_in[0];
    const void*  e = d_in[1];
    const float* W[5] = {(const float*)d_in[2], (const float*)d_in[4],
                         (const float*)d_in[6], (const float*)d_in[8],
                         (const float*)d_in[10]};
    const float* b[5] = {(const float*)d_in[3], (const float*)d_in[5],
                         (const float*)d_in[7], (const float*)d_in[9],
                         (const float*)d_in[11]};
    float* out = (float*)d_out;

    bf16 *ahi, *alo, *bhi, *blo, *whi, *wlo;
    float* tm;
    cudaGetSymbolAddress((void**)&ahi, g_Ahi);
    cudaGetSymbolAddress((void**)&alo, g_Alo);
    cudaGetSymbolAddress((void**)&bhi, g_Bhi);
    cudaGetSymbolAddress((void**)&blo, g_Blo);
    cudaGetSymbolAddress((void**)&whi, g_Whi);
    cudaGetSymbolAddress((void**)&wlo, g_Wlo);
    cudaGetSymbolAddress((void**)&tm, g_tmp);

    const int SMEM_SZ = 2 * STG;   // 98304
    static int attr_set = 0;
    if (!attr_set) {
        cudaFuncSetAttribute(bgemm_kernel, cudaFuncAttributeMaxDynamicSharedMemorySize, SMEM_SZ);
        attr_set = 1;
    }

    // graph preprocessing
    detect_idx_kernel<<<1, 1>>>(e);
    zero_deg_kernel<<<(N_NODES + 255) / 256, 256>>>();
    count_deg_kernel<<<(N_EDGES + 255) / 256, 256>>>(e);
    block_sum_kernel<<<GSCAN, 1024>>>();
    scan_partials_kernel<<<1, 1>>>();
    scatter_scan_kernel<<<GSCAN, 1024>>>();
    fill_csr_kernel<<<(N_EDGES + 255) / 256, 256>>>(e);

    const int dims[6] = {512, 2048, 1024, 512, 256, 128};
    long long woff[5];
    {
        long long o = 0;
        for (int l = 0; l < 5; l++) { woff[l] = o; o += (long long)dims[l] * dims[l + 1]; }
    }
    for (int l = 0; l < 5; l++) {
        int cnt = dims[l] * dims[l + 1];
        convert_w_kernel<<<(cnt + 255) / 256, 256>>>(W[l], woff[l], dims[l], dims[l + 1]);
    }

    int gy = (N_NODES + 255) / 256;

    // L1: aggregate x first (d=512, linearity), then GEMM with fused
    //     bias+relu+hi/lo epilogue straight into buffer B (2048-wide).
    aggx_kernel<<<N_NODES, 128>>>(x, ahi, alo);
    {
        dim3 grid(2048 / 128, gy);
        bgemm_kernel<<<grid, 512, SMEM_SZ>>>(ahi, alo, whi + woff[0], wlo + woff[0],
                                             nullptr, b[0], bhi, blo,
                                             N_NODES, 2048, 512, 1);
    }

    // L2..L5: GEMM -> tmp fp32 -> aggregate (+bias, +relu/split or final fp32)
    bf16* inhi[4] = {bhi, ahi, bhi, ahi};
    bf16* inlo[4] = {blo, alo, blo, alo};
    bf16* othi[4] = {ahi, bhi, ahi, nullptr};
    bf16* otlo[4] = {alo, blo, alo, nullptr};
    for (int l = 1; l < 5; l++) {
        int K = dims[l], N = dims[l + 1];
        dim3 grid(N / 128, gy);
        bgemm_kernel<<<grid, 512, SMEM_SZ>>>(inhi[l - 1], inlo[l - 1],
                                             whi + woff[l], wlo + woff[l],
                                             tm, nullptr, nullptr, nullptr,
                                             N_NODES, N, K, 0);
        if (N >= 512) {
            agg_wide_kernel<<<N_NODES, 128>>>(tm, b[l], othi[l - 1], otlo[l - 1], N);
        } else {
            agg_narrow_kernel<<<(N_NODES + 3) / 4, 128>>>(tm, b[l], out,
                                                          othi[l - 1], otlo[l - 1],
                                                          N, l == 4 ? 1 : 0);
        }
    }
}

// round 14
// speedup vs baseline: 1.6513x; 1.6513x over previous
#include <cuda_runtime.h>
#include <cuda_bf16.h>
#include <cstdint>

#define N_NODES 50000
#define N_EDGES 320000
#define GSCAN   ((N_NODES + 1023) / 1024)

// ---------------- static scratch (no allocations allowed) ----------------
__device__ float g_A[(size_t)N_NODES * 1024];   // activation buffer A (tf32-rounded fp32)
__device__ float g_B[(size_t)N_NODES * 2048];   // activation buffer B (tf32-rounded fp32)
__device__ float g_tmp[(size_t)N_NODES * 1024]; // GEMM fp32 out (pre-agg), max d=1024
__device__ float g_W[4 * 1024 * 1024];          // transposed weights (tf32-rounded fp32)

__device__ int   g_deg[N_NODES];
__device__ float g_dinv[N_NODES];
__device__ int   g_rowptr[N_NODES + 1];
__device__ int   g_fill[N_NODES];
__device__ int   g_csr[N_EDGES];
__device__ int   g_bsum[64];
__device__ int   g_is64;

// ---------------- tf32 rounding helper ----------------
__device__ __forceinline__ float to_tf32(float v) {
    uint32_t u;
    asm("cvt.rna.tf32.f32 %0, %1;" : "=r"(u) : "f"(v));
    return __uint_as_float(u);
}

// ---------------- index dtype handling ----------------
__global__ void detect_idx_kernel(const void* e) {
    const int* w = (const int*)e;
    int all0 = 1;
    for (int i = 1; i < 64; i += 2)
        if (w[i] != 0) all0 = 0;
    g_is64 = all0;
}

__device__ __forceinline__ int get_idx(const void* e, long long i) {
    if (g_is64) return (int)((const long long*)e)[i];
    return ((const int*)e)[i];
}

// ---------------- graph preprocessing ----------------
__global__ void zero_deg_kernel() {
    int i = blockIdx.x * blockDim.x + threadIdx.x;
    if (i < N_NODES) g_deg[i] = 0;
}

__global__ void count_deg_kernel(const void* e) {
    int i = blockIdx.x * blockDim.x + threadIdx.x;
    if (i >= N_EDGES) return;
    int dst = get_idx(e, (long long)N_EDGES + i);
    atomicAdd(&g_deg[dst], 1);
}

__global__ void block_sum_kernel() {
    int i = blockIdx.x * 1024 + threadIdx.x;
    int v = (i < N_NODES) ? g_deg[i] : 0;
    int lane = threadIdx.x & 31, warp = threadIdx.x >> 5;
#pragma unroll
    for (int off = 16; off > 0; off >>= 1) v += __shfl_down_sync(0xffffffffu, v, off);
    __shared__ int ws[32];
    if (lane == 0) ws[warp] = v;
    __syncthreads();
    if (warp == 0) {
        int s = ws[lane];
#pragma unroll
        for (int off = 16; off > 0; off >>= 1) s += __shfl_down_sync(0xffffffffu, s, off);
        if (lane == 0) g_bsum[blockIdx.x] = s;
    }
}

__global__ void scan_partials_kernel() {
    int acc = 0;
    for (int i = 0; i < GSCAN; i++) { int t = g_bsum[i]; g_bsum[i] = acc; acc += t; }
    g_rowptr[N_NODES] = acc;
}

__global__ void scatter_scan_kernel() {
    int i = blockIdx.x * 1024 + threadIdx.x;
    int v = (i < N_NODES) ? g_deg[i] : 0;
    int lane = threadIdx.x & 31, warp = threadIdx.x >> 5;
    int incl = v;
#pragma unroll
    for (int off = 1; off < 32; off <<= 1) {
        int t = __shfl_up_sync(0xffffffffu, incl, off);
        if (lane >= off) incl += t;
    }
    __shared__ int ws[32];
    if (lane == 31) ws[warp] = incl;
    __syncthreads();
    if (warp == 0) {
        int s = ws[lane];
#pragma unroll
        for (int off = 1; off < 32; off <<= 1) {
            int t = __shfl_up_sync(0xffffffffu, s, off);
            if (lane >= off) s += t;
        }
        ws[lane] = s;
    }
    __syncthreads();
    int wbase = (warp == 0) ? 0 : ws[warp - 1];
    int excl = g_bsum[blockIdx.x] + wbase + incl - v;
    if (i < N_NODES) {
        g_rowptr[i] = excl;
        g_fill[i]   = excl;
        g_dinv[i]   = rsqrtf((float)v + 1.0f);
    }
}

__global__ void fill_csr_kernel(const void* e) {
    int i = blockIdx.x * blockDim.x + threadIdx.x;
    if (i >= N_EDGES) return;
    int src = get_idx(e, i);
    int dst = get_idx(e, (long long)N_EDGES + i);
    int pos = atomicAdd(&g_fill[dst], 1);
    g_csr[pos] = src;
}

// ---------------- weight conversion: W [K,N] -> Wt [N,K] tf32 ----------------
__global__ void convert_w_kernel(const float* __restrict__ W, long long off, int K, int N) {
    int idx = blockIdx.x * blockDim.x + threadIdx.x;
    if (idx >= K * N) return;
    int k = idx / N, n = idx % N;
    g_W[off + (size_t)n * K + k] = to_tf32(W[idx]);
}

// ---------------- tf32 tensor-core GEMM (mma.sync.m16n8k8) ----------------
// C[M,N] = A[M,K] @ Wt[N,K]^T, operands tf32-rounded fp32.
// 128x128x32 tiles, 256 threads (8 warps of 64x32), cp.async 2-stage,
// 128B rows with 8-chunk xor swizzle, ldmatrix.x4 (b16 view == tf32 frag).
// mode 0: store fp32 C.  mode 1: fused bias+relu+tf32-round into O.
__device__ __forceinline__ void ldm4(uint32_t* r, uint32_t addr) {
    asm volatile("ldmatrix.sync.aligned.m8n8.x4.shared.b16 {%0,%1,%2,%3}, [%4];"
                 : "=r"(r[0]), "=r"(r[1]), "=r"(r[2]), "=r"(r[3]) : "r"(addr));
}

__device__ __forceinline__ void mma_tf32(float* c, const uint32_t* a, const uint32_t* b) {
    asm volatile(
        "mma.sync.aligned.m16n8k8.row.col.f32.tf32.tf32.f32 "
        "{%0,%1,%2,%3},{%4,%5,%6,%7},{%8,%9},{%0,%1,%2,%3};"
        : "+f"(c[0]), "+f"(c[1]), "+f"(c[2]), "+f"(c[3])
        : "r"(a[0]), "r"(a[1]), "r"(a[2]), "r"(a[3]), "r"(b[0]), "r"(b[1]));
}

__device__ __forceinline__ void cp16(uint32_t dst, const void* src, bool pred) {
    int sz = pred ? 16 : 0;
    asm volatile("cp.async.cg.shared.global [%0], [%1], 16, %2;\n"
                 :: "r"(dst), "l"(src), "r"(sz));
}

// stage (32KB): A rows[0,16K): 128 x 128B; B rows[16K,32K): 128 x 128B.
// row r: 8 chunks of 16B (4 tf32); logical chunk c at physical c ^ (r & 7).
__device__ __forceinline__ void load_stage(
    uint32_t sbase, int stage,
    const float* __restrict__ A, const float* __restrict__ B,
    int bm, int bn, int k0, int M, int K, int tid)
{
    uint32_t st = sbase + stage * 32768;
#pragma unroll
    for (int h = 0; h < 4; h++) {
        int i = tid + h * 256;
        int row = i >> 3, c = i & 7;
        uint32_t doff = (uint32_t)(row * 128 + (c ^ (row & 7)) * 16);
        long arow = bm + row;
        bool av = arow < M;
        long ar = av ? arow : 0;
        cp16(st + doff, A + (size_t)ar * K + k0 + c * 4, av);
    }
#pragma unroll
    for (int h = 0; h < 4; h++) {
        int i = tid + h * 256;
        int row = i >> 3, c = i & 7;
        uint32_t doff = (uint32_t)(row * 128 + (c ^ (row & 7)) * 16);
        cp16(st + 16384 + doff, B + (size_t)(bn + row) * K + k0 + c * 4, true);
    }
    asm volatile("cp.async.commit_group;\n");
}

__global__ void __launch_bounds__(256)
bgemm_kernel(const float* __restrict__ A, const float* __restrict__ W,
             float* __restrict__ C, const float* __restrict__ bias,
             float* __restrict__ O, int M, int N, int K, int mode)
{
    extern __shared__ __align__(16) char smem[];
    uint32_t sbase = (uint32_t)__cvta_generic_to_shared(smem);

    int tid  = threadIdx.x;
    int lane = tid & 31, wid = tid >> 5;
    int wm = (wid >> 2) * 64;
    int wn = (wid & 3) * 32;
    int bm = blockIdx.y * 128;
    int bn = blockIdx.x * 128;

    float acc[4][4][4];
#pragma unroll
    for (int i = 0; i < 4; i++)
#pragma unroll
        for (int j = 0; j < 4; j++)
#pragma unroll
            for (int r = 0; r < 4; r++) acc[i][j][r] = 0.f;

    int nk = K >> 5;
    load_stage(sbase, 0, A, W, bm, bn, 0, M, K, tid);

    int lr = lane & 15, lc = lane >> 4;

    for (int kt = 0; kt < nk; kt++) {
        if (kt + 1 < nk) {
            load_stage(sbase, (kt + 1) & 1, A, W, bm, bn, (kt + 1) * 32, M, K, tid);
            asm volatile("cp.async.wait_group 1;\n");
        } else {
            asm volatile("cp.async.wait_group 0;\n");
        }
        __syncthreads();

        uint32_t st = sbase + (kt & 1) * 32768;
#pragma unroll
        for (int s = 0; s < 4; s++) {          // 4 k8-steps per 32-k tile
            int c = s * 2 + lc;                // logical 16B chunk
            uint32_t bf[4][2];
#pragma unroll
            for (int p = 0; p < 2; p++) {
                int row = wn + p * 16 + lr;
                uint32_t r4[4];
                ldm4(r4, st + 16384 + (uint32_t)(row * 128 + ((c ^ (row & 7)) << 4)));
                bf[2 * p][0] = r4[0];     bf[2 * p][1] = r4[2];
                bf[2 * p + 1][0] = r4[1]; bf[2 * p + 1][1] = r4[3];
            }
#pragma unroll
            for (int fm = 0; fm < 4; fm++) {
                int row = wm + fm * 16 + lr;
                uint32_t a4[4];
                ldm4(a4, st + (uint32_t)(row * 128 + ((c ^ (row & 7)) << 4)));
#pragma unroll
                for (int fn = 0; fn < 4; fn++)
                    mma_tf32(acc[fm][fn], a4, bf[fn]);
            }
        }
        __syncthreads();
    }

    int g = lane >> 2, tg = lane & 3;
    if (mode == 0) {
#pragma unroll
        for (int fm = 0; fm < 4; fm++) {
#pragma unroll
            for (int fn = 0; fn < 4; fn++) {
                int row = bm + wm + fm * 16 + g;
                int col = bn + wn + fn * 8 + tg * 2;
                if (row < M)
                    *(float2*)&C[(size_t)row * N + col] = make_float2(acc[fm][fn][0], acc[fm][fn][1]);
                if (row + 8 < M)
                    *(float2*)&C[(size_t)(row + 8) * N + col] = make_float2(acc[fm][fn][2], acc[fm][fn][3]);
            }
        }
    } else {
#pragma unroll
        for (int fm = 0; fm < 4; fm++) {
#pragma unroll
            for (int fn = 0; fn < 4; fn++) {
                int col = bn + wn + fn * 8 + tg * 2;
                float2 bv = *(const float2*)&bias[col];
#pragma unroll
                for (int h = 0; h < 2; h++) {
                    int row = bm + wm + fm * 16 + g + h * 8;
                    if (row >= M) continue;
                    float v0 = to_tf32(fmaxf(acc[fm][fn][h * 2]     + bv.x, 0.f));
                    float v1 = to_tf32(fmaxf(acc[fm][fn][h * 2 + 1] + bv.y, 0.f));
                    *(float2*)&O[(size_t)row * N + col] = make_float2(v0, v1);
                }
            }
        }
    }
}

// ---------------- aggregation of raw input x (d=512) -> tf32 fp32 ----------------
__global__ void __launch_bounds__(128)
aggx_kernel(const float* __restrict__ x, float* __restrict__ o)
{
    const int d = 512;
    int node = blockIdx.x;
    int tid  = threadIdx.x;
    float di = g_dinv[node];
    int beg = g_rowptr[node];
    int end = g_rowptr[node + 1];

    float selfn = di * di;
    float4 v = ((const float4*)(x + (size_t)node * d))[tid];
    float4 acc = make_float4(v.x * selfn, v.y * selfn, v.z * selfn, v.w * selfn);

    for (int e = beg; e < end; e++) {
        int src = g_csr[e];
        float nrm = di * g_dinv[src];
        float4 w = ((const float4*)(x + (size_t)src * d))[tid];
        acc.x += w.x * nrm; acc.y += w.y * nrm;
        acc.z += w.z * nrm; acc.w += w.w * nrm;
    }

    float4 r = make_float4(to_tf32(acc.x), to_tf32(acc.y), to_tf32(acc.z), to_tf32(acc.w));
    ((float4*)(o + (size_t)node * d))[tid] = r;
}

// ---------------- CSR aggregation, wide (d = 512 or 1024), block per node --------
__global__ void __launch_bounds__(128)
agg_wide_kernel(const float* __restrict__ tmp, const float* __restrict__ bias,
                float* __restrict__ o, int d)
{
    int node = blockIdx.x;
    int tid  = threadIdx.x;
    float di = g_dinv[node];
    int beg = g_rowptr[node];
    int end = g_rowptr[node + 1];
    int nc4 = d >> 2;

    float4 acc[2];
    float selfn = di * di;
    const float4* selfrow = (const float4*)(tmp + (size_t)node * d);
#pragma unroll
    for (int j = 0; j < 2; j++) {
        int c = tid + j * 128;
        if (c < nc4) {
            float4 v = selfrow[c];
            acc[j] = make_float4(v.x * selfn, v.y * selfn, v.z * selfn, v.w * selfn);
        } else acc[j] = make_float4(0.f, 0.f, 0.f, 0.f);
    }

    for (int e = beg; e < end; e++) {
        int src = g_csr[e];
        float nrm = di * g_dinv[src];
        const float4* row = (const float4*)(tmp + (size_t)src * d);
#pragma unroll
        for (int j = 0; j < 2; j++) {
            int c = tid + j * 128;
            if (c < nc4) {
                float4 v = row[c];
                acc[j].x += v.x * nrm; acc[j].y += v.y * nrm;
                acc[j].z += v.z * nrm; acc[j].w += v.w * nrm;
            }
        }
    }

    const float4* b4 = (const float4*)bias;
#pragma unroll
    for (int j = 0; j < 2; j++) {
        int c = tid + j * 128;
        if (c >= nc4) continue;
        float4 bv = b4[c];
        float4 r = make_float4(to_tf32(fmaxf(acc[j].x + bv.x, 0.f)),
                               to_tf32(fmaxf(acc[j].y + bv.y, 0.f)),
                               to_tf32(fmaxf(acc[j].z + bv.z, 0.f)),
                               to_tf32(fmaxf(acc[j].w + bv.w, 0.f)));
        ((float4*)(o + (size_t)node * d))[c] = r;
    }
}

// ---------------- CSR aggregation, narrow (d = 128 or 256), warp per node --------
__global__ void __launch_bounds__(128)
agg_narrow_kernel(const float* __restrict__ tmp, const float* __restrict__ bias,
                  float* __restrict__ outf, float* __restrict__ o, int d, int last)
{
    int node = blockIdx.x * 4 + (threadIdx.x >> 5);
    if (node >= N_NODES) return;
    int lane = threadIdx.x & 31;
    int nc4 = d >> 2;   // 32 or 64
    float di = g_dinv[node];
    int beg = g_rowptr[node];
    int end = g_rowptr[node + 1];

    float4 acc[2];
    float selfn = di * di;
    const float4* selfrow = (const float4*)(tmp + (size_t)node * d);
#pragma unroll
    for (int j = 0; j < 2; j++) {
        int c = lane + j * 32;
        if (c < nc4) {
            float4 v = selfrow[c];
            acc[j] = make_float4(v.x * selfn, v.y * selfn, v.z * selfn, v.w * selfn);
        } else acc[j] = make_float4(0.f, 0.f, 0.f, 0.f);
    }

    for (int e = beg; e < end; e++) {
        int src = g_csr[e];
        float nrm = di * g_dinv[src];
        const float4* row = (const float4*)(tmp + (size_t)src * d);
#pragma unroll
        for (int j = 0; j < 2; j++) {
            int c = lane + j * 32;
            if (c < nc4) {
                float4 v = row[c];
                acc[j].x += v.x * nrm; acc[j].y += v.y * nrm;
                acc[j].z += v.z * nrm; acc[j].w += v.w * nrm;
            }
        }
    }

    const float4* b4 = (const float4*)bias;
#pragma unroll
    for (int j = 0; j < 2; j++) {
        int c = lane + j * 32;
        if (c >= nc4) continue;
        float4 bv = b4[c];
        float4 r = make_float4(acc[j].x + bv.x, acc[j].y + bv.y,
                               acc[j].z + bv.z, acc[j].w + bv.w);
        if (last) {
            ((float4*)(outf + (size_t)node * d))[c] = r;
        } else {
            r = make_float4(to_tf32(fmaxf(r.x, 0.f)), to_tf32(fmaxf(r.y, 0.f)),
                            to_tf32(fmaxf(r.z, 0.f)), to_tf32(fmaxf(r.w, 0.f)));
            ((float4*)(o + (size_t)node * d))[c] = r;
        }
    }
}

// ---------------- launch ----------------
extern "C" void kernel_launch(void* const* d_in, const int* in_sizes, int n_in,
                              void* d_out, int out_size) {
    const float* x = (const float*)d_in[0];
    const void*  e = d_in[1];
    const float* W[5] = {(const float*)d_in[2], (const float*)d_in[4],
                         (const float*)d_in[6], (const float*)d_in[8],
                         (const float*)d_in[10]};
    const float* b[5] = {(const float*)d_in[3], (const float*)d_in[5],
                         (const float*)d_in[7], (const float*)d_in[9],
                         (const float*)d_in[11]};
    float* out = (float*)d_out;

    float *bufA, *bufB, *w, *tm;
    cudaGetSymbolAddress((void**)&bufA, g_A);
    cudaGetSymbolAddress((void**)&bufB, g_B);
    cudaGetSymbolAddress((void**)&w, g_W);
    cudaGetSymbolAddress((void**)&tm, g_tmp);

    static int attr_set = 0;
    if (!attr_set) {
        cudaFuncSetAttribute(bgemm_kernel, cudaFuncAttributeMaxDynamicSharedMemorySize, 65536);
        attr_set = 1;
    }

    // graph preprocessing
    detect_idx_kernel<<<1, 1>>>(e);
    zero_deg_kernel<<<(N_NODES + 255) / 256, 256>>>();
    count_deg_kernel<<<(N_EDGES + 255) / 256, 256>>>(e);
    block_sum_kernel<<<GSCAN, 1024>>>();
    scan_partials_kernel<<<1, 1>>>();
    scatter_scan_kernel<<<GSCAN, 1024>>>();
    fill_csr_kernel<<<(N_EDGES + 255) / 256, 256>>>(e);

    const int dims[6] = {512, 2048, 1024, 512, 256, 128};
    long long woff[5];
    {
        long long o = 0;
        for (int l = 0; l < 5; l++) { woff[l] = o; o += (long long)dims[l] * dims[l + 1]; }
    }
    for (int l = 0; l < 5; l++) {
        int cnt = dims[l] * dims[l + 1];
        convert_w_kernel<<<(cnt + 255) / 256, 256>>>(W[l], woff[l], dims[l], dims[l + 1]);
    }

    int gy = (N_NODES + 127) / 128;

    // L1: aggregate x first (d=512, linearity), then GEMM with fused
    //     bias+relu+tf32 epilogue straight into buffer B (2048-wide).
    aggx_kernel<<<N_NODES, 128>>>(x, bufA);
    {
        dim3 grid(2048 / 128, gy);
        bgemm_kernel<<<grid, 256, 65536>>>(bufA, w + woff[0], nullptr, b[0], bufB,
                                           N_NODES, 2048, 512, 1);
    }

    // L2..L5: GEMM -> tmp fp32 -> aggregate (+bias, +relu/tf32 or final fp32)
    float* in4[4] = {bufB, bufA, bufB, bufA};
    float* ot4[4] = {bufA, bufB, bufA, nullptr};
    for (int l = 1; l < 5; l++) {
        int K = dims[l], N = dims[l + 1];
        dim3 grid(N / 128, gy);
        bgemm_kernel<<<grid, 256, 65536>>>(in4[l - 1], w + woff[l], tm, nullptr, nullptr,
                                           N_NODES, N, K, 0);
        if (N >= 512) {
            agg_wide_kernel<<<N_NODES, 128>>>(tm, b[l], ot4[l - 1], N);
        } else {
            agg_narrow_kernel<<<(N_NODES + 3) / 4, 128>>>(tm, b[l], out, ot4[l - 1],
                                                          N, l == 4 ? 1 : 0);
        }
    }
}